// round 2
// baseline (speedup 1.0000x reference)
#include <cuda_runtime.h>
#include <math.h>

#define NB 128
#define D_IMG 8192
#define D_LANG 4096
#define KC 256            // k elements per gram chunk
#define KP (KC/2)         // f32x2 k-pairs per chunk = 128
#define NCH_IMG (D_IMG/KC)    // 32
#define NCH_LANG (D_LANG/KC)  // 16
#define GRAM_BLOCKS (3*NCH_IMG + 3*NCH_LANG)  // 96 + 48 = 144
#define GRAM_SMEM (2*KP*64*sizeof(float2))    // 128 KB

// ---------- scratch (static device memory; no allocations) ----------
__device__ float d_part_img[NCH_IMG * NB * NB];    // per-chunk partial Gram (image)
__device__ float d_part_lang[NCH_LANG * NB * NB];  // per-chunk partial Gram (lang)
__device__ float d_pre[2 * NB * NB];               // pre-softmax matrices
__device__ float d_lse[2 * NB];                    // row logsumexp
__device__ float d_norm[2 * NB];                   // row squared norms

#define FFMA2(d, a, b, c) \
    asm("fma.rn.f32x2 %0, %1, %2, %3;" : "=l"(d) : "l"(a), "l"(b), "l"(c))

// ---------- kernel 1: row squared norms ----------
__global__ __launch_bounds__(256) void k_norm(const float* __restrict__ img,
                                              const float* __restrict__ lang) {
    int b = blockIdx.x;
    int m = b >> 7;
    int row = b & 127;
    const float* F = m ? lang : img;
    int D = m ? D_LANG : D_IMG;
    const float4* p = (const float4*)(F + (size_t)row * D);
    int n4 = D >> 2;
    float s = 0.f;
    for (int i = threadIdx.x; i < n4; i += 256) {
        float4 v = p[i];
        s += v.x * v.x + v.y * v.y + v.z * v.z + v.w * v.w;
    }
#pragma unroll
    for (int o = 16; o; o >>= 1) s += __shfl_xor_sync(~0u, s, o);
    __shared__ float sm[8];
    int lane = threadIdx.x & 31, w = threadIdx.x >> 5;
    if (lane == 0) sm[w] = s;
    __syncthreads();
    if (threadIdx.x == 0) {
        float t = 0.f;
#pragma unroll
        for (int i = 0; i < 8; i++) t += sm[i];
        d_norm[m * NB + row] = t;
    }
}

// ---------- kernel 2: partial Gram tiles (A * A^T), f32x2 packed ----------
__global__ __launch_bounds__(256, 1) void k_gram(const float* __restrict__ img,
                                                 const float* __restrict__ lang) {
    extern __shared__ float2 sm2[];   // As2[KP][64] then Bs2[KP][64]
    int bid = blockIdx.x;
    int m, tp, ch;
    if (bid < 3 * NCH_IMG) { m = 0; tp = bid / NCH_IMG; ch = bid % NCH_IMG; }
    else { int b2 = bid - 3 * NCH_IMG; m = 1; tp = b2 / NCH_LANG; ch = b2 % NCH_LANG; }

    const float* F = m ? lang : img;
    int D = m ? D_LANG : D_IMG;
    float* part = m ? d_part_lang : d_part_img;

    int ti = (tp == 2) ? 1 : 0;   // (0,0),(0,1),(1,1)
    int tj = (tp == 0) ? 0 : 1;
    int ri = ti * 64, rj = tj * 64;
    int k0 = ch * KC;
    int t = threadIdx.x;
    bool diag = (ti == tj);

    float2* As2 = sm2;
    float2* Bs2 = sm2 + KP * 64;

    // load tiles into [kpair][row] float2 layout
    {
        const float4* Fp = (const float4*)F;
        int D4 = D >> 2;
        int kq0 = k0 >> 2;
#pragma unroll
        for (int l = 0; l < 16; l++) {
            int li = t + 256 * l;
            int row = li >> 6;
            int q = li & 63;
            float4 v = Fp[(size_t)(ri + row) * D4 + kq0 + q];
            As2[(2 * q) * 64 + row] = make_float2(v.x, v.y);
            As2[(2 * q + 1) * 64 + row] = make_float2(v.z, v.w);
        }
        if (!diag) {
#pragma unroll
            for (int l = 0; l < 16; l++) {
                int li = t + 256 * l;
                int row = li >> 6;
                int q = li & 63;
                float4 v = Fp[(size_t)(rj + row) * D4 + kq0 + q];
                Bs2[(2 * q) * 64 + row] = make_float2(v.x, v.y);
                Bs2[(2 * q + 1) * 64 + row] = make_float2(v.z, v.w);
            }
        }
    }
    __syncthreads();

    const unsigned long long* Au = (const unsigned long long*)As2;
    const unsigned long long* Bu = diag ? Au : (const unsigned long long*)Bs2;
    int tx = t & 15, ty = t >> 4;   // rows: ty+16*ii, cols: tx+16*jj

    unsigned long long acc[4][4];
#pragma unroll
    for (int ii = 0; ii < 4; ii++)
#pragma unroll
        for (int jj = 0; jj < 4; jj++) acc[ii][jj] = 0ull;

#pragma unroll 2
    for (int kp = 0; kp < KP; kp++) {
        unsigned long long a[4], bb[4];
#pragma unroll
        for (int ii = 0; ii < 4; ii++) a[ii] = Au[kp * 64 + ty + 16 * ii];
#pragma unroll
        for (int jj = 0; jj < 4; jj++) bb[jj] = Bu[kp * 64 + tx + 16 * jj];
#pragma unroll
        for (int ii = 0; ii < 4; ii++)
#pragma unroll
            for (int jj = 0; jj < 4; jj++)
                FFMA2(acc[ii][jj], a[ii], bb[jj], acc[ii][jj]);
    }

    float g[4][4];
#pragma unroll
    for (int ii = 0; ii < 4; ii++)
#pragma unroll
        for (int jj = 0; jj < 4; jj++) {
            unsigned long long v = acc[ii][jj];
            g[ii][jj] = __uint_as_float((unsigned int)v) +
                        __uint_as_float((unsigned int)(v >> 32));
        }

    float* base = part + ch * NB * NB;
#pragma unroll
    for (int ii = 0; ii < 4; ii++)
#pragma unroll
        for (int jj = 0; jj < 4; jj++) {
            int r = ri + ty + 16 * ii;
            int c = rj + tx + 16 * jj;
            base[r * NB + c] = g[ii][jj];
        }

    if (tp == 1) {  // mirror (1,0) quadrant via smem-staged transpose
        __syncthreads();
        float* T = (float*)sm2;   // [64][68]
#pragma unroll
        for (int ii = 0; ii < 4; ii++)
#pragma unroll
            for (int jj = 0; jj < 4; jj++)
                T[(tx + 16 * jj) * 68 + (ty + 16 * ii)] = g[ii][jj];
        __syncthreads();
#pragma unroll
        for (int l = 0; l < 16; l++) {
            int li = t + 256 * l;
            int cc = li >> 6;
            int rr = li & 63;
            base[(64 + cc) * NB + rr] = T[cc * 68 + rr];
        }
    }
}

// ---------- kernel 3: reduce partials -> pre matrix + row lse ----------
__global__ __launch_bounds__(128) void k_rowlse(const float* __restrict__ temp) {
    int b = blockIdx.x;
    int m = b >> 7;
    int i = b & 127;
    int j = threadIdx.x;  // 128 threads
    const float* part = m ? d_part_lang : d_part_img;
    int nch = m ? NCH_LANG : NCH_IMG;

    float g = 0.f;
#pragma unroll 8
    for (int c = 0; c < nch; c++) g += part[c * NB * NB + i * NB + j];

    float ni = d_norm[m * NB + i];
    float nj = d_norm[m * NB + j];
    float expT = expf(temp[0]);
    float sq = ni + nj - 2.f * g;
    float pre = (j == i) ? 0.f : -sqrtf(fmaxf(sq, 0.f)) * expT;
    d_pre[m * NB * NB + i * NB + j] = pre;

    float e = expf(pre);
#pragma unroll
    for (int o = 16; o; o >>= 1) e += __shfl_xor_sync(~0u, e, o);
    __shared__ float sw[4];
    if ((j & 31) == 0) sw[j >> 5] = e;
    __syncthreads();
    if (j == 0) {
        float s = sw[0] + sw[1] + sw[2] + sw[3];
        d_lse[m * NB + i] = logf(s);
    }
}

// ---------- kernel 4: KL combine + column sum ----------
__global__ __launch_bounds__(512) void k_out(float* __restrict__ out) {
    __shared__ float s_lse[256];
    __shared__ float s_red[512];
    int t = threadIdx.x;
    if (t < 256) s_lse[t] = d_lse[t];
    __syncthreads();
    int j = t & 127;
    int rr = t >> 7;  // 0..3
    float acc = 0.f;
#pragma unroll 8
    for (int i = rr; i < NB; i += 4) {
        float af = d_pre[i * NB + j] - s_lse[i];               // image = A_f
        float ag = d_pre[NB * NB + i * NB + j] - s_lse[128 + i]; // lang = A_g
        acc += expf(ag) * (ag - af);
    }
    s_red[t] = acc;
    __syncthreads();
    if (rr == 0)
        out[j] = s_red[j] + s_red[128 + j] + s_red[256 + j] + s_red[384 + j];
}

extern "C" void kernel_launch(void* const* d_in, const int* in_sizes, int n_in,
                              void* d_out, int out_size) {
    const float* img = (const float*)d_in[0];
    const float* lang = (const float*)d_in[1];
    const float* temp = (const float*)d_in[2];
    float* out = (float*)d_out;
    (void)in_sizes; (void)n_in; (void)out_size;

    cudaFuncSetAttribute(k_gram, cudaFuncAttributeMaxDynamicSharedMemorySize,
                         (int)GRAM_SMEM);

    k_norm<<<256, 256>>>(img, lang);
    k_gram<<<GRAM_BLOCKS, 256, GRAM_SMEM>>>(img, lang);
    k_rowlse<<<256, 128>>>(temp);
    k_out<<<1, 512>>>(out);
}

// round 3
// speedup vs baseline: 1.0940x; 1.0940x over previous
#include <cuda_runtime.h>
#include <math.h>

#define NB 128
#define D_IMG 8192
#define D_LANG 4096
#define KC 256            // k elements per gram chunk
#define KP (KC/2)         // f32x2 k-pairs per chunk = 128
#define NCH_IMG (D_IMG/KC)    // 32
#define NCH_LANG (D_LANG/KC)  // 16
#define GRAM_BLOCKS (3*NCH_IMG + 3*NCH_LANG)  // 96 + 48 = 144
#define GRAM_SMEM (2*KP*64*sizeof(float2))    // 128 KB

// ---------- scratch (static device memory; no allocations) ----------
__device__ float d_part_img[NCH_IMG * NB * NB];    // per-chunk partial Gram (image)
__device__ float d_part_lang[NCH_LANG * NB * NB];  // per-chunk partial Gram (lang)
__device__ float d_pre[2 * NB * NB];               // pre-softmax matrices
__device__ float d_lse[2 * NB];                    // row logsumexp
__device__ float d_norm[2 * NB];                   // row squared norms (= Gram diag)

#define FFMA2(d, a, b, c) \
    asm("fma.rn.f32x2 %0, %1, %2, %3;" : "=l"(d) : "l"(a), "l"(b), "l"(c))

// ---------- kernel 1: partial Gram tiles (A * A^T), f32x2 packed ----------
__global__ __launch_bounds__(256, 1) void k_gram(const float* __restrict__ img,
                                                 const float* __restrict__ lang) {
    extern __shared__ float2 sm2[];   // As2[KP][64] then Bs2[KP][64]
    int bid = blockIdx.x;
    int m, tp, ch;
    if (bid < 3 * NCH_IMG) { m = 0; tp = bid / NCH_IMG; ch = bid % NCH_IMG; }
    else { int b2 = bid - 3 * NCH_IMG; m = 1; tp = b2 / NCH_LANG; ch = b2 % NCH_LANG; }

    const float* F = m ? lang : img;
    int D = m ? D_LANG : D_IMG;
    float* part = m ? d_part_lang : d_part_img;

    int ti = (tp == 2) ? 1 : 0;   // (0,0),(0,1),(1,1)
    int tj = (tp == 0) ? 0 : 1;
    int ri = ti * 64, rj = tj * 64;
    int k0 = ch * KC;
    int t = threadIdx.x;
    bool diag = (ti == tj);

    float2* As2 = sm2;
    float2* Bs2 = sm2 + KP * 64;

    // load tiles into [kpair][row] float2 layout
    {
        const float4* Fp = (const float4*)F;
        int D4 = D >> 2;
        int kq0 = k0 >> 2;
#pragma unroll
        for (int l = 0; l < 16; l++) {
            int li = t + 256 * l;
            int row = li >> 6;
            int q = li & 63;
            float4 v = Fp[(size_t)(ri + row) * D4 + kq0 + q];
            As2[(2 * q) * 64 + row] = make_float2(v.x, v.y);
            As2[(2 * q + 1) * 64 + row] = make_float2(v.z, v.w);
        }
        if (!diag) {
#pragma unroll
            for (int l = 0; l < 16; l++) {
                int li = t + 256 * l;
                int row = li >> 6;
                int q = li & 63;
                float4 v = Fp[(size_t)(rj + row) * D4 + kq0 + q];
                Bs2[(2 * q) * 64 + row] = make_float2(v.x, v.y);
                Bs2[(2 * q + 1) * 64 + row] = make_float2(v.z, v.w);
            }
        }
    }
    __syncthreads();

    const unsigned long long* Au = (const unsigned long long*)As2;
    const unsigned long long* Bu = diag ? Au : (const unsigned long long*)Bs2;
    int tx = t & 15, ty = t >> 4;   // rows: ty+16*ii, cols: tx+16*jj

    unsigned long long acc[4][4];
#pragma unroll
    for (int ii = 0; ii < 4; ii++)
#pragma unroll
        for (int jj = 0; jj < 4; jj++) acc[ii][jj] = 0ull;

#pragma unroll 2
    for (int kp = 0; kp < KP; kp++) {
        unsigned long long a[4], bb[4];
#pragma unroll
        for (int ii = 0; ii < 4; ii++) a[ii] = Au[kp * 64 + ty + 16 * ii];
#pragma unroll
        for (int jj = 0; jj < 4; jj++) bb[jj] = Bu[kp * 64 + tx + 16 * jj];
#pragma unroll
        for (int ii = 0; ii < 4; ii++)
#pragma unroll
            for (int jj = 0; jj < 4; jj++)
                FFMA2(acc[ii][jj], a[ii], bb[jj], acc[ii][jj]);
    }

    float g[4][4];
#pragma unroll
    for (int ii = 0; ii < 4; ii++)
#pragma unroll
        for (int jj = 0; jj < 4; jj++) {
            unsigned long long v = acc[ii][jj];
            g[ii][jj] = __uint_as_float((unsigned int)v) +
                        __uint_as_float((unsigned int)(v >> 32));
        }

    float* base = part + ch * NB * NB;
#pragma unroll
    for (int ii = 0; ii < 4; ii++)
#pragma unroll
        for (int jj = 0; jj < 4; jj++) {
            int r = ri + ty + 16 * ii;
            int c = rj + tx + 16 * jj;
            base[r * NB + c] = g[ii][jj];
        }

    if (tp == 1) {  // mirror (1,0) quadrant via smem-staged transpose
        __syncthreads();
        float* T = (float*)sm2;   // [64][68]
#pragma unroll
        for (int ii = 0; ii < 4; ii++)
#pragma unroll
            for (int jj = 0; jj < 4; jj++)
                T[(tx + 16 * jj) * 68 + (ty + 16 * ii)] = g[ii][jj];
        __syncthreads();
#pragma unroll
        for (int l = 0; l < 16; l++) {
            int li = t + 256 * l;
            int cc = li >> 6;
            int rr = li & 63;
            base[(64 + cc) * NB + rr] = T[cc * 68 + rr];
        }
    }
}

// ---------- kernel 2: norms = Gram diagonal (sum partial diags) ----------
__global__ __launch_bounds__(128) void k_diag() {
    int m = blockIdx.x;
    int j = threadIdx.x;
    const float* part = m ? d_part_lang : d_part_img;
    int nch = m ? NCH_LANG : NCH_IMG;
    float s = 0.f;
#pragma unroll 16
    for (int c = 0; c < nch; c++) s += part[c * NB * NB + j * NB + j];
    d_norm[m * NB + j] = s;
}

// ---------- kernel 3: reduce partials -> pre matrix + row lse ----------
__global__ __launch_bounds__(128) void k_rowlse(const float* __restrict__ temp) {
    int b = blockIdx.x;
    int m = b >> 7;
    int i = b & 127;
    int j = threadIdx.x;  // 128 threads
    const float* part = m ? d_part_lang : d_part_img;
    int nch = m ? NCH_LANG : NCH_IMG;

    float g = 0.f;
#pragma unroll 8
    for (int c = 0; c < nch; c++) g += part[c * NB * NB + i * NB + j];

    float ni = d_norm[m * NB + i];
    float nj = d_norm[m * NB + j];
    float expT = __expf(temp[0]);
    float sq = ni + nj - 2.f * g;
    float pre = (j == i) ? 0.f : -sqrtf(fmaxf(sq, 0.f)) * expT;
    d_pre[m * NB * NB + i * NB + j] = pre;

    float e = __expf(pre);
#pragma unroll
    for (int o = 16; o; o >>= 1) e += __shfl_xor_sync(~0u, e, o);
    __shared__ float sw[4];
    if ((j & 31) == 0) sw[j >> 5] = e;
    __syncthreads();
    if (j == 0) {
        float s = sw[0] + sw[1] + sw[2] + sw[3];
        d_lse[m * NB + i] = __logf(s);
    }
}

// ---------- kernel 4: KL combine + column sum (one block per column) ----------
__global__ __launch_bounds__(128) void k_out(float* __restrict__ out) {
    int j = blockIdx.x;
    int i = threadIdx.x;
    float af = d_pre[i * NB + j] - d_lse[i];                 // image = A_f
    float ag = d_pre[NB * NB + i * NB + j] - d_lse[128 + i]; // lang  = A_g
    float v = __expf(ag) * (ag - af);
#pragma unroll
    for (int o = 16; o; o >>= 1) v += __shfl_xor_sync(~0u, v, o);
    __shared__ float sw[4];
    if ((i & 31) == 0) sw[i >> 5] = v;
    __syncthreads();
    if (i == 0) out[j] = sw[0] + sw[1] + sw[2] + sw[3];
}

extern "C" void kernel_launch(void* const* d_in, const int* in_sizes, int n_in,
                              void* d_out, int out_size) {
    const float* img = (const float*)d_in[0];
    const float* lang = (const float*)d_in[1];
    const float* temp = (const float*)d_in[2];
    float* out = (float*)d_out;
    (void)in_sizes; (void)n_in; (void)out_size;

    cudaFuncSetAttribute(k_gram, cudaFuncAttributeMaxDynamicSharedMemorySize,
                         (int)GRAM_SMEM);

    k_gram<<<GRAM_BLOCKS, 256, GRAM_SMEM>>>(img, lang);
    k_diag<<<2, 128>>>();
    k_rowlse<<<256, 128>>>(temp);
    k_out<<<128, 128>>>(out);
}